// round 1
// baseline (speedup 1.0000x reference)
#include <cuda_runtime.h>
#include <cstdint>

#define BATCH 1024
#define NUM_CLS 58

// ---------------- device scratch (no allocations allowed) ----------------
__device__ uint4 g_a1[BATCH * 15 * 15];   // packed signs after conv0+pool  [b][py*15+px][4 words]
__device__ uint4 g_a2[BATCH * 6 * 6];     // packed signs after binconv1+pool
__device__ uint4 g_a3[BATCH * 3 * 3];     // packed signs after binconv2+pool
__device__ unsigned g_pw1[9 * 4 * 128];   // packed w1 signs, layout [tap][word][oc]
__device__ unsigned g_pw2[9 * 4 * 128];
__device__ unsigned g_pw3[9 * 4 * 128];
__device__ unsigned g_pw4[4 * 128];       // layout [word][oc]

// ---------------- weight sign packing ----------------
__device__ __forceinline__ void pack9(const float* __restrict__ w, unsigned* __restrict__ pw, int id) {
    // id = (tap*4 + wi)*128 + oc ; bit b of word = sign(w[oc][wi*32+b][tap]) >= 0
    int oc = id & 127;
    int r  = id >> 7;
    int wi  = r & 3;
    int tap = r >> 2;
    unsigned v = 0;
#pragma unroll
    for (int b = 0; b < 32; b++) {
        if (w[(oc * 128 + wi * 32 + b) * 9 + tap] >= 0.0f) v |= (1u << b);
    }
    pw[id] = v;
}

__global__ void pack_weights_kernel(const float* __restrict__ w1, const float* __restrict__ w2,
                                    const float* __restrict__ w3, const float* __restrict__ w4) {
    int id = blockIdx.x * blockDim.x + threadIdx.x;
    if (id < 4608) {
        pack9(w1, g_pw1, id);
    } else if (id < 9216) {
        pack9(w2, g_pw2, id - 4608);
    } else if (id < 13824) {
        pack9(w3, g_pw3, id - 9216);
    } else if (id < 14336) {
        int j = id - 13824;       // [wi][oc]
        int oc = j & 127;
        int wi = j >> 7;
        unsigned v = 0;
#pragma unroll
        for (int b = 0; b < 32; b++) {
            if (w4[oc * 128 + wi * 32 + b] >= 0.0f) v |= (1u << b);
        }
        g_pw4[j] = v;
    }
}

// ---------------- stage A: fp32 conv0 (3->128, 3x3) + maxpool2x2 + sign + pack ----------------
// block = image, 256 threads = 8 warps. warp -> (channel group cg = warp&3, half = warp>>2)
__global__ __launch_bounds__(256) void convA_kernel(const float* __restrict__ x,
                                                    const float* __restrict__ w0) {
    __shared__ float xs[3 * 32 * 32];
    int b = blockIdx.x;
    const float* xb = x + (size_t)b * 3072;
    for (int i = threadIdx.x; i < 3072; i += 256) xs[i] = xb[i];
    __syncthreads();

    int warp = threadIdx.x >> 5;
    int lane = threadIdx.x & 31;
    int cg   = warp & 3;
    int half = warp >> 2;
    int oc   = cg * 32 + lane;

    float wr[27];
#pragma unroll
    for (int k = 0; k < 27; k++) wr[k] = w0[oc * 27 + k];

    unsigned* a1w = (unsigned*)g_a1;

    for (int p = half; p < 225; p += 2) {
        int py = p / 15, px = p - py * 15;
        int y0 = 2 * py, x0 = 2 * px;
        float xp[3][4][4];
#pragma unroll
        for (int c = 0; c < 3; c++)
#pragma unroll
            for (int dy = 0; dy < 4; dy++)
#pragma unroll
                for (int dx = 0; dx < 4; dx++)
                    xp[c][dy][dx] = xs[c * 1024 + (y0 + dy) * 32 + (x0 + dx)];

        float best = -3.4e38f;
#pragma unroll
        for (int cy = 0; cy < 2; cy++)
#pragma unroll
            for (int cx = 0; cx < 2; cx++) {
                float acc = 0.0f;
#pragma unroll
                for (int c = 0; c < 3; c++)
#pragma unroll
                    for (int ky = 0; ky < 3; ky++)
#pragma unroll
                        for (int kx = 0; kx < 3; kx++)
                            acc += xp[c][cy + ky][cx + kx] * wr[c * 9 + ky * 3 + kx];
                best = fmaxf(best, acc);
            }

        unsigned word = __ballot_sync(0xffffffffu, best >= 0.0f);
        if (lane == 0) a1w[((size_t)b * 225 + p) * 4 + cg] = word;
    }
}

// ---------------- stage B: binconv1 (3x3) on 15x15 -> 13x13, pool 2x2 -> 6x6, sign+pack -------
// block = image, 256 threads = 8 warps. warp -> (cg = warp>>1, parity = warp&1)
__global__ __launch_bounds__(256) void binconv1_kernel() {
    __shared__ uint4 a1s[225];
    __shared__ unsigned w1s[9 * 4 * 128];
    int b = blockIdx.x;
    if (threadIdx.x < 225) a1s[threadIdx.x] = g_a1[(size_t)b * 225 + threadIdx.x];
    for (int i = threadIdx.x; i < 4608; i += 256) w1s[i] = g_pw1[i];
    __syncthreads();

    int warp = threadIdx.x >> 5;
    int lane = threadIdx.x & 31;
    int cg  = warp >> 1;
    int par = warp & 1;
    int oc  = cg * 32 + lane;

    uint4 wr[9];
#pragma unroll
    for (int tap = 0; tap < 9; tap++) {
        wr[tap].x = w1s[(tap * 4 + 0) * 128 + oc];
        wr[tap].y = w1s[(tap * 4 + 1) * 128 + oc];
        wr[tap].z = w1s[(tap * 4 + 2) * 128 + oc];
        wr[tap].w = w1s[(tap * 4 + 3) * 128 + oc];
    }

    unsigned* a2w = (unsigned*)g_a2;

    for (int p = par; p < 36; p += 2) {
        int py = p / 6, px = p - py * 6;
        int y0 = 2 * py, x0 = 2 * px;
        uint4 xp[16];
#pragma unroll
        for (int dy = 0; dy < 4; dy++)
#pragma unroll
            for (int dx = 0; dx < 4; dx++)
                xp[dy * 4 + dx] = a1s[(y0 + dy) * 15 + (x0 + dx)];

        int smin = 1 << 30;
#pragma unroll
        for (int cy = 0; cy < 2; cy++)
#pragma unroll
            for (int cx = 0; cx < 2; cx++) {
                int s = 0;
#pragma unroll
                for (int ky = 0; ky < 3; ky++)
#pragma unroll
                    for (int kx = 0; kx < 3; kx++) {
                        uint4 xv = xp[(cy + ky) * 4 + (cx + kx)];
                        uint4 wv = wr[ky * 3 + kx];
                        s += __popc(xv.x ^ wv.x) + __popc(xv.y ^ wv.y) +
                             __popc(xv.z ^ wv.z) + __popc(xv.w ^ wv.w);
                    }
                smin = min(smin, s);
            }
        // dot = 1152 - 2*smin ; sign bit = (dot >= 0)
        unsigned word = __ballot_sync(0xffffffffu, smin <= 576);
        if (lane == 0) a2w[((size_t)b * 36 + p) * 4 + cg] = word;
    }
}

// ---------------- stage C: binconv2 (3x3) on 6x6 -> 4x4, pool k2 s1 -> 3x3, sign+pack --------
// block = image, 128 threads = 4 warps. warp = cg, each warp does all 9 pooled pixels.
__global__ __launch_bounds__(128) void binconv2_kernel() {
    __shared__ uint4 a2s[36];
    __shared__ unsigned w2s[9 * 4 * 128];
    int b = blockIdx.x;
    if (threadIdx.x < 36) a2s[threadIdx.x] = g_a2[(size_t)b * 36 + threadIdx.x];
    for (int i = threadIdx.x; i < 4608; i += 128) w2s[i] = g_pw2[i];
    __syncthreads();

    int cg   = threadIdx.x >> 5;
    int lane = threadIdx.x & 31;
    int oc   = cg * 32 + lane;

    uint4 wr[9];
#pragma unroll
    for (int tap = 0; tap < 9; tap++) {
        wr[tap].x = w2s[(tap * 4 + 0) * 128 + oc];
        wr[tap].y = w2s[(tap * 4 + 1) * 128 + oc];
        wr[tap].z = w2s[(tap * 4 + 2) * 128 + oc];
        wr[tap].w = w2s[(tap * 4 + 3) * 128 + oc];
    }

    unsigned* a3w = (unsigned*)g_a3;

    for (int p = 0; p < 9; p++) {
        int py = p / 3, px = p - py * 3;
        uint4 xp[16];
#pragma unroll
        for (int dy = 0; dy < 4; dy++)
#pragma unroll
            for (int dx = 0; dx < 4; dx++)
                xp[dy * 4 + dx] = a2s[(py + dy) * 6 + (px + dx)];

        int smin = 1 << 30;
#pragma unroll
        for (int cy = 0; cy < 2; cy++)
#pragma unroll
            for (int cx = 0; cx < 2; cx++) {
                int s = 0;
#pragma unroll
                for (int ky = 0; ky < 3; ky++)
#pragma unroll
                    for (int kx = 0; kx < 3; kx++) {
                        uint4 xv = xp[(cy + ky) * 4 + (cx + kx)];
                        uint4 wv = wr[ky * 3 + kx];
                        s += __popc(xv.x ^ wv.x) + __popc(xv.y ^ wv.y) +
                             __popc(xv.z ^ wv.z) + __popc(xv.w ^ wv.w);
                    }
                smin = min(smin, s);
            }
        unsigned word = __ballot_sync(0xffffffffu, smin <= 576);
        if (lane == 0) a3w[((size_t)b * 9 + p) * 4 + cg] = word;
    }
}

// ---------------- stage D: binconv3 (3x3 -> 1x1) + binconv4 (1x1) + relu + fp32 1x1 + softmax -
// block = image, 128 threads.
__global__ __launch_bounds__(128) void head_kernel(const float* __restrict__ w5,
                                                   float* __restrict__ out) {
    __shared__ uint4 a3s[9];
    __shared__ unsigned w3s[9 * 4 * 128];
    __shared__ unsigned pw4s[4 * 128];
    __shared__ unsigned s4[4];
    __shared__ float rs[128];
    __shared__ float lg[NUM_CLS];

    int b = blockIdx.x;
    int tid = threadIdx.x;
    if (tid < 9) a3s[tid] = g_a3[(size_t)b * 9 + tid];
    for (int i = tid; i < 4608; i += 128) w3s[i] = g_pw3[i];
    for (int i = tid; i < 512; i += 128) pw4s[i] = g_pw4[i];
    __syncthreads();

    int oc   = tid;
    int lane = tid & 31;
    int warp = tid >> 5;

    // binconv3: full 3x3 receptive field -> one dot per output channel
    int s = 0;
#pragma unroll
    for (int tap = 0; tap < 9; tap++) {
        uint4 xv = a3s[tap];
        s += __popc(xv.x ^ w3s[(tap * 4 + 0) * 128 + oc]);
        s += __popc(xv.y ^ w3s[(tap * 4 + 1) * 128 + oc]);
        s += __popc(xv.z ^ w3s[(tap * 4 + 2) * 128 + oc]);
        s += __popc(xv.w ^ w3s[(tap * 4 + 3) * 128 + oc]);
    }
    unsigned word = __ballot_sync(0xffffffffu, s <= 576);  // sign(1152 - 2s)
    if (lane == 0) s4[warp] = word;
    __syncthreads();

    // binconv4 (1x1) + relu
    int t = 0;
#pragma unroll
    for (int wi = 0; wi < 4; wi++) t += __popc(s4[wi] ^ pw4s[wi * 128 + oc]);
    rs[oc] = fmaxf((float)(128 - 2 * t), 0.0f);
    __syncthreads();

    // fp32 1x1 conv to NUM_CLS logits
    if (tid < NUM_CLS) {
        float acc = 0.0f;
#pragma unroll 8
        for (int o = 0; o < 128; o++) acc += w5[tid * 128 + o] * rs[o];
        lg[tid] = acc;
    }
    __syncthreads();

    // softmax over NUM_CLS
    if (tid < NUM_CLS) {
        float m = -3.4e38f;
        for (int j = 0; j < NUM_CLS; j++) m = fmaxf(m, lg[j]);
        float den = 0.0f;
        for (int j = 0; j < NUM_CLS; j++) den += expf(lg[j] - m);
        out[(size_t)b * NUM_CLS + tid] = expf(lg[tid] - m) / den;
    }
}

// ---------------- launch ----------------
extern "C" void kernel_launch(void* const* d_in, const int* in_sizes, int n_in,
                              void* d_out, int out_size) {
    const float* x  = (const float*)d_in[0];
    const float* w0 = (const float*)d_in[1];
    const float* w1 = (const float*)d_in[2];
    const float* w2 = (const float*)d_in[3];
    const float* w3 = (const float*)d_in[4];
    const float* w4 = (const float*)d_in[5];
    const float* w5 = (const float*)d_in[6];
    float* out = (float*)d_out;

    pack_weights_kernel<<<56, 256>>>(w1, w2, w3, w4);
    convA_kernel<<<BATCH, 256>>>(x, w0);
    binconv1_kernel<<<BATCH, 256>>>();
    binconv2_kernel<<<BATCH, 128>>>();
    head_kernel<<<BATCH, 128>>>(w5, out);
}

// round 3
// speedup vs baseline: 1.0910x; 1.0910x over previous
#include <cuda_runtime.h>
#include <cstdint>

#define BATCH 1024
#define NUM_CLS 58

// ---------------- device scratch (no allocations allowed) ----------------
__device__ uint4 g_a1[BATCH * 15 * 15];   // packed signs after conv0+pool  [b][py*15+px][4 words]
__device__ unsigned g_pw1[9 * 4 * 128];   // packed w1 signs, layout [tap][word][oc]
__device__ unsigned g_pw2[9 * 4 * 128];
__device__ unsigned g_pw3[9 * 4 * 128];
__device__ unsigned g_pw4[4 * 128];       // layout [word][oc]

// ---------------- weight sign packing ----------------
__device__ __forceinline__ void pack9(const float* __restrict__ w, unsigned* __restrict__ pw, int id) {
    // id = (tap*4 + wi)*128 + oc ; bit b of word = sign(w[oc][wi*32+b][tap]) >= 0
    int oc = id & 127;
    int r  = id >> 7;
    int wi  = r & 3;
    int tap = r >> 2;
    unsigned v = 0;
#pragma unroll
    for (int b = 0; b < 32; b++) {
        if (w[(oc * 128 + wi * 32 + b) * 9 + tap] >= 0.0f) v |= (1u << b);
    }
    pw[id] = v;
}

__global__ void pack_weights_kernel(const float* __restrict__ w1, const float* __restrict__ w2,
                                    const float* __restrict__ w3, const float* __restrict__ w4) {
    int id = blockIdx.x * blockDim.x + threadIdx.x;
    if (id < 4608) {
        pack9(w1, g_pw1, id);
    } else if (id < 9216) {
        pack9(w2, g_pw2, id - 4608);
    } else if (id < 13824) {
        pack9(w3, g_pw3, id - 9216);
    } else if (id < 14336) {
        int j = id - 13824;       // [wi][oc]
        int oc = j & 127;
        int wi = j >> 7;
        unsigned v = 0;
#pragma unroll
        for (int b = 0; b < 32; b++) {
            if (w4[oc * 128 + wi * 32 + b] >= 0.0f) v |= (1u << b);
        }
        g_pw4[j] = v;
    }
}

// ---------------- stage A: fp32 conv0 (3->128, 3x3) + maxpool2x2 + sign + pack ----------------
// block = image, 256 threads = 8 warps. warp -> (channel group cg = warp&3, half = warp>>2)
__global__ __launch_bounds__(256) void convA_kernel(const float* __restrict__ x,
                                                    const float* __restrict__ w0) {
    __shared__ float xs[3 * 32 * 32];
    int b = blockIdx.x;
    const float4* xb4 = (const float4*)(x + (size_t)b * 3072);
    float4* xs4 = (float4*)xs;
    for (int i = threadIdx.x; i < 768; i += 256) xs4[i] = xb4[i];
    __syncthreads();

    int warp = threadIdx.x >> 5;
    int lane = threadIdx.x & 31;
    int cg   = warp & 3;
    int half = warp >> 2;
    int oc   = cg * 32 + lane;

    float wr[27];
#pragma unroll
    for (int k = 0; k < 27; k++) wr[k] = w0[oc * 27 + k];

    unsigned* a1w = (unsigned*)g_a1;

    for (int p = half; p < 225; p += 2) {
        int py = p / 15, px = p - py * 15;
        int y0 = 2 * py, x0 = 2 * px;   // x0 even -> float2 aligned

        float acc0 = 0.f, acc1 = 0.f, acc2 = 0.f, acc3 = 0.f;
#pragma unroll
        for (int c = 0; c < 3; c++) {
            float e[4][4];
#pragma unroll
            for (int dy = 0; dy < 4; dy++) {
                const float2* r2 = (const float2*)&xs[c * 1024 + (y0 + dy) * 32 + x0];
                float2 lo = r2[0];
                float2 hi = r2[1];
                e[dy][0] = lo.x; e[dy][1] = lo.y; e[dy][2] = hi.x; e[dy][3] = hi.y;
            }
#pragma unroll
            for (int ky = 0; ky < 3; ky++)
#pragma unroll
                for (int kx = 0; kx < 3; kx++) {
                    float w = wr[c * 9 + ky * 3 + kx];
                    acc0 += e[0 + ky][0 + kx] * w;
                    acc1 += e[0 + ky][1 + kx] * w;
                    acc2 += e[1 + ky][0 + kx] * w;
                    acc3 += e[1 + ky][1 + kx] * w;
                }
        }
        float best = fmaxf(fmaxf(acc0, acc1), fmaxf(acc2, acc3));

        unsigned word = __ballot_sync(0xffffffffu, best >= 0.0f);
        if (lane == 0) a1w[((size_t)b * 225 + p) * 4 + cg] = word;
    }
}

// ---------------- fused stages B+C+D ----------------
// block = image, 256 threads.
// Phase 1: binconv1 (3x3, 15x15->13x13) + pool2x2 -> 6x6 signs in smem
// Phase 2: binconv2 (3x3, 6x6->4x4) + pool k2 s1 -> 3x3 signs in smem   (w3 prefetch overlapped)
// Phase 3: binconv3 (3x3->1x1) + binconv4 (1x1) + relu + fp32 1x1 + softmax
__global__ __launch_bounds__(256) void fusedBCD_kernel(const float* __restrict__ w5,
                                                       float* __restrict__ out) {
    __shared__ uint4 a1s[225];
    __shared__ unsigned wA[4608];     // w1, later w3
    __shared__ unsigned wB[4608];     // w2
    __shared__ unsigned pw4s[512];
    __shared__ uint4 a2v[36];
    __shared__ uint4 a3v[9];
    __shared__ unsigned s4w[4];
    __shared__ float rs[128];
    __shared__ float lg[NUM_CLS];

    int b   = blockIdx.x;
    int tid = threadIdx.x;
    int warp = tid >> 5;
    int lane = tid & 31;

    if (tid < 225) a1s[tid] = g_a1[(size_t)b * 225 + tid];
#pragma unroll
    for (int i = 0; i < 18; i++) {
        wA[tid + 256 * i] = g_pw1[tid + 256 * i];
        wB[tid + 256 * i] = g_pw2[tid + 256 * i];
    }
    pw4s[tid]       = g_pw4[tid];
    pw4s[tid + 256] = g_pw4[tid + 256];
    __syncthreads();

    // ---- phase 1: binconv1. 8 warps: cg = warp>>1, parity = warp&1 ----
    {
        int cg  = warp >> 1;
        int par = warp & 1;
        int oc  = cg * 32 + lane;

        uint4 wr[9];
#pragma unroll
        for (int tap = 0; tap < 9; tap++) {
            wr[tap].x = wA[(tap * 4 + 0) * 128 + oc];
            wr[tap].y = wA[(tap * 4 + 1) * 128 + oc];
            wr[tap].z = wA[(tap * 4 + 2) * 128 + oc];
            wr[tap].w = wA[(tap * 4 + 3) * 128 + oc];
        }

        for (int p = par; p < 36; p += 2) {
            int py = p / 6, px = p - py * 6;
            int y0 = 2 * py, x0 = 2 * px;

            int smin = 1 << 30;
#pragma unroll
            for (int cy = 0; cy < 2; cy++)
#pragma unroll
                for (int cx = 0; cx < 2; cx++) {
                    int s = 0;
#pragma unroll
                    for (int ky = 0; ky < 3; ky++)
#pragma unroll
                        for (int kx = 0; kx < 3; kx++) {
                            uint4 xv = a1s[(y0 + cy + ky) * 15 + (x0 + cx + kx)];
                            uint4 wv = wr[ky * 3 + kx];
                            s += __popc(xv.x ^ wv.x) + __popc(xv.y ^ wv.y) +
                                 __popc(xv.z ^ wv.z) + __popc(xv.w ^ wv.w);
                        }
                    smin = min(smin, s);
                }
            // dot = 1152 - 2*smin ; sign bit = (dot >= 0)
            unsigned word = __ballot_sync(0xffffffffu, smin <= 576);
            if (lane == 0) ((unsigned*)a2v)[p * 4 + cg] = word;
        }
    }
    __syncthreads();

    // ---- phase 2: binconv2 with wB; overlap prefetch of w3 into registers ----
    unsigned t3[18];
#pragma unroll
    for (int i = 0; i < 18; i++) t3[i] = g_pw3[tid + 256 * i];

    {
        int cg   = warp & 3;
        int half = warp >> 2;
        int oc   = cg * 32 + lane;

        uint4 wr[9];
#pragma unroll
        for (int tap = 0; tap < 9; tap++) {
            wr[tap].x = wB[(tap * 4 + 0) * 128 + oc];
            wr[tap].y = wB[(tap * 4 + 1) * 128 + oc];
            wr[tap].z = wB[(tap * 4 + 2) * 128 + oc];
            wr[tap].w = wB[(tap * 4 + 3) * 128 + oc];
        }

        for (int p = half; p < 9; p += 2) {
            int py = p / 3, px = p - py * 3;

            int smin = 1 << 30;
#pragma unroll
            for (int cy = 0; cy < 2; cy++)
#pragma unroll
                for (int cx = 0; cx < 2; cx++) {
                    int s = 0;
#pragma unroll
                    for (int ky = 0; ky < 3; ky++)
#pragma unroll
                        for (int kx = 0; kx < 3; kx++) {
                            uint4 xv = a2v[(py + cy + ky) * 6 + (px + cx + kx)];
                            uint4 wv = wr[ky * 3 + kx];
                            s += __popc(xv.x ^ wv.x) + __popc(xv.y ^ wv.y) +
                                 __popc(xv.z ^ wv.z) + __popc(xv.w ^ wv.w);
                        }
                    smin = min(smin, s);
                }
            unsigned word = __ballot_sync(0xffffffffu, smin <= 576);
            if (lane == 0) ((unsigned*)a3v)[p * 4 + cg] = word;
        }
    }

    // commit w3 prefetch into wA (binconv1 readers are past the earlier sync)
#pragma unroll
    for (int i = 0; i < 18; i++) wA[tid + 256 * i] = t3[i];
    __syncthreads();

    // ---- phase 3: head (threads 0..127 = output channel) ----
    if (tid < 128) {
        int oc = tid;
        // binconv3: full 3x3 receptive field -> one dot per output channel
        int s = 0;
#pragma unroll
        for (int tap = 0; tap < 9; tap++) {
            uint4 xv = a3v[tap];
            s += __popc(xv.x ^ wA[(tap * 4 + 0) * 128 + oc]);
            s += __popc(xv.y ^ wA[(tap * 4 + 1) * 128 + oc]);
            s += __popc(xv.z ^ wA[(tap * 4 + 2) * 128 + oc]);
            s += __popc(xv.w ^ wA[(tap * 4 + 3) * 128 + oc]);
        }
        unsigned word = __ballot_sync(0xffffffffu, s <= 576);  // sign(1152 - 2s)
        if (lane == 0) s4w[warp] = word;
    }
    __syncthreads();

    if (tid < 128) {
        int oc = tid;
        // binconv4 (1x1) + relu
        int t = 0;
#pragma unroll
        for (int wi = 0; wi < 4; wi++) t += __popc(s4w[wi] ^ pw4s[wi * 128 + oc]);
        rs[oc] = fmaxf((float)(128 - 2 * t), 0.0f);
    }
    __syncthreads();

    // fp32 1x1 conv to NUM_CLS logits
    if (tid < NUM_CLS) {
        float acc = 0.0f;
#pragma unroll 8
        for (int o = 0; o < 128; o++) acc += w5[tid * 128 + o] * rs[o];
        lg[tid] = acc;
    }
    __syncthreads();

    // softmax over NUM_CLS
    if (tid < NUM_CLS) {
        float m = -3.4e38f;
        for (int j = 0; j < NUM_CLS; j++) m = fmaxf(m, lg[j]);
        float den = 0.0f;
        for (int j = 0; j < NUM_CLS; j++) den += expf(lg[j] - m);
        out[(size_t)b * NUM_CLS + tid] = expf(lg[tid] - m) / den;
    }
}

// ---------------- launch ----------------
extern "C" void kernel_launch(void* const* d_in, const int* in_sizes, int n_in,
                              void* d_out, int out_size) {
    const float* x  = (const float*)d_in[0];
    const float* w0 = (const float*)d_in[1];
    const float* w1 = (const float*)d_in[2];
    const float* w2 = (const float*)d_in[3];
    const float* w3 = (const float*)d_in[4];
    const float* w4 = (const float*)d_in[5];
    const float* w5 = (const float*)d_in[6];
    float* out = (float*)d_out;

    pack_weights_kernel<<<56, 256>>>(w1, w2, w3, w4);
    convA_kernel<<<BATCH, 256>>>(x, w0);
    fusedBCD_kernel<<<BATCH, 256>>>(w5, out);
}